// round 1
// baseline (speedup 1.0000x reference)
#include <cuda_runtime.h>
#include <cuda_bf16.h>

// Problem constants (shapes fixed by the dataset)
#define NN   8192
#define EE   65536
#define INC  64
#define OUTC 16
#define EF   8
#define L1   48
#define L2   32

// Combined column counts for the fused node transforms
// Layer 1: Y1 (EF*L1=384) + Z1 (48) + R1 (48) = 480 cols, K=64
// Layer 2: Y2 (EF*L2=256) + Z2 (32) + R2 (32) = 320 cols, K=48
#define C1TOT 480
#define C2TOT 320

#define NPB 16  // nodes per block in node-transform kernels

// ---------------- scratch (device globals; no allocation allowed) ----------
__device__ float dY1[(size_t)NN * EF * L1];   // [n][f*48+j]  12.6 MB
__device__ float dZ1[NN * L1];
__device__ float dAgg1[NN * L1];
__device__ float dY2[(size_t)NN * EF * L2];   // [n][f*32+j]  8.4 MB
__device__ float dZ2[NN * L2];
__device__ float dAgg2[NN * L2];
__device__ float dDeg[NN];
__device__ float dG[NN * 2 * OUTC];           // [n][c], c<16 mu, c>=16 ls
__device__ float dW1T[C1TOT * 64];            // [c][k]
__device__ float dW2T[C2TOT * 48];            // [c][k]
__device__ float dWgT[32 * 32];               // [c][k]

// ---------------- kernel 0: weight pre-transpose ---------------------------
__global__ void prep_weights(const float* __restrict__ nn1_w, const float* __restrict__ nn1_b,
                             const float* __restrict__ root1,
                             const float* __restrict__ nn2_w, const float* __restrict__ nn2_b,
                             const float* __restrict__ root2,
                             const float* __restrict__ mu_w,  const float* __restrict__ ls_w) {
    int idx = blockIdx.x * blockDim.x + threadIdx.x;
    if (idx < C1TOT * 64) {
        int c = idx >> 6, k = idx & 63;
        float v;
        if (c < EF * L1)            { int f = c / L1, j = c % L1; v = nn1_w[f * (INC * L1) + k * L1 + j]; }
        else if (c < EF * L1 + L1)  { int j = c - EF * L1;        v = nn1_b[k * L1 + j]; }
        else                        { int j = c - EF * L1 - L1;   v = root1[k * L1 + j]; }
        dW1T[idx] = v;
    }
    int i2 = idx - C1TOT * 64;
    if (i2 >= 0 && i2 < C2TOT * 48) {
        int c = i2 / 48, k = i2 % 48;
        float v;
        if (c < EF * L2)            { int f = c / L2, j = c % L2; v = nn2_w[f * (L1 * L2) + k * L2 + j]; }
        else if (c < EF * L2 + L2)  { int j = c - EF * L2;        v = nn2_b[k * L2 + j]; }
        else                        { int j = c - EF * L2 - L2;   v = root2[k * L2 + j]; }
        dW2T[i2] = v;
    }
    int i3 = i2 - C2TOT * 48;
    if (i3 >= 0 && i3 < 32 * 32) {
        int c = i3 >> 5, k = i3 & 31;
        dWgT[i3] = (c < OUTC) ? mu_w[k * OUTC + c] : ls_w[k * OUTC + (c - OUTC)];
    }
}

// ---------------- kernel 1: node transform layer 1 -------------------------
// Computes Y1 = x@W_f (per f), Z1 = x@B1, agg1 := x@root1 + bias1 ; deg := 1
__global__ __launch_bounds__(256) void node1_kernel(const float* __restrict__ x,
                                                    const float* __restrict__ bias1) {
    __shared__ float xs[NPB * 64];
    int n0 = blockIdx.x * NPB;
    int t = threadIdx.x;
    // load 16 rows x 64 floats = 256 float4 (one per thread), coalesced
    ((float4*)xs)[t] = ((const float4*)(x + (size_t)n0 * 64))[t];
    if (t < NPB) dDeg[n0 + t] = 1.0f;
    __syncthreads();

    for (int c = t; c < C1TOT; c += 256) {
        float acc[NPB];
#pragma unroll
        for (int n = 0; n < NPB; n++) acc[n] = 0.0f;
        const float4* w4 = (const float4*)(dW1T + c * 64);
#pragma unroll
        for (int k4 = 0; k4 < 16; k4++) {
            float4 w = w4[k4];
#pragma unroll
            for (int n = 0; n < NPB; n++) {
                float4 xv = ((const float4*)(xs + n * 64))[k4];
                acc[n] += xv.x * w.x + xv.y * w.y + xv.z * w.z + xv.w * w.w;
            }
        }
        if (c < EF * L1) {
#pragma unroll
            for (int n = 0; n < NPB; n++) dY1[(size_t)(n0 + n) * (EF * L1) + c] = acc[n];
        } else if (c < EF * L1 + L1) {
            int j = c - EF * L1;
#pragma unroll
            for (int n = 0; n < NPB; n++) dZ1[(n0 + n) * L1 + j] = acc[n];
        } else {
            int j = c - EF * L1 - L1;
            float b = bias1[j];
#pragma unroll
            for (int n = 0; n < NPB; n++) dAgg1[(n0 + n) * L1 + j] = acc[n] + b;
        }
    }
}

// ---------------- kernel 2: edge scatter layer 1 ---------------------------
__global__ void edge1_kernel(const int* __restrict__ ei, const float* __restrict__ ea) {
    int idx = blockIdx.x * blockDim.x + threadIdx.x;
    if (idx >= EE * L1) return;
    int e = idx / L1;
    int j = idx - e * L1;
    int s = ei[e];
    int d = ei[EE + e];
    const float* eav = ea + e * EF;
    const float* y = dY1 + (size_t)s * (EF * L1) + j;
    float m = dZ1[s * L1 + j];
#pragma unroll
    for (int f = 0; f < EF; f++) m += eav[f] * y[f * L1];
    atomicAdd(&dAgg1[d * L1 + j], m);
    if (j == 0) atomicAdd(&dDeg[d], 1.0f);
}

// ---------------- kernel 3: node transform layer 2 -------------------------
__global__ __launch_bounds__(256) void node2_kernel(const float* __restrict__ bias2) {
    __shared__ float hs[NPB * 48];
    int n0 = blockIdx.x * NPB;
    int t = threadIdx.x;
    if (t < NPB * 48 / 4) {
        float4 v = ((const float4*)(dAgg1 + n0 * L1))[t];
        v.x = fmaxf(v.x, 0.f); v.y = fmaxf(v.y, 0.f);
        v.z = fmaxf(v.z, 0.f); v.w = fmaxf(v.w, 0.f);
        ((float4*)hs)[t] = v;
    }
    __syncthreads();

    for (int c = t; c < C2TOT; c += 256) {
        float acc[NPB];
#pragma unroll
        for (int n = 0; n < NPB; n++) acc[n] = 0.0f;
        const float4* w4 = (const float4*)(dW2T + c * 48);
#pragma unroll
        for (int k4 = 0; k4 < 12; k4++) {
            float4 w = w4[k4];
#pragma unroll
            for (int n = 0; n < NPB; n++) {
                float4 xv = ((const float4*)(hs + n * 48))[k4];
                acc[n] += xv.x * w.x + xv.y * w.y + xv.z * w.z + xv.w * w.w;
            }
        }
        if (c < EF * L2) {
#pragma unroll
            for (int n = 0; n < NPB; n++) dY2[(size_t)(n0 + n) * (EF * L2) + c] = acc[n];
        } else if (c < EF * L2 + L2) {
            int j = c - EF * L2;
#pragma unroll
            for (int n = 0; n < NPB; n++) dZ2[(n0 + n) * L2 + j] = acc[n];
        } else {
            int j = c - EF * L2 - L2;
            float b = bias2[j];
#pragma unroll
            for (int n = 0; n < NPB; n++) dAgg2[(n0 + n) * L2 + j] = acc[n] + b;
        }
    }
}

// ---------------- kernel 4: edge scatter layer 2 ---------------------------
__global__ void edge2_kernel(const int* __restrict__ ei, const float* __restrict__ ea) {
    int idx = blockIdx.x * blockDim.x + threadIdx.x;
    if (idx >= EE * L2) return;
    int e = idx >> 5;
    int j = idx & 31;
    int s = ei[e];
    int d = ei[EE + e];
    const float* eav = ea + e * EF;
    const float* y = dY2 + (size_t)s * (EF * L2) + j;
    float m = dZ2[s * L2 + j];
#pragma unroll
    for (int f = 0; f < EF; f++) m += eav[f] * y[f * L2];
    atomicAdd(&dAgg2[d * L2 + j], m);
}

// ---------------- kernel 5: h2 relu + head GEMV + out init -----------------
__global__ void node3_kernel(const float* __restrict__ mu_b, const float* __restrict__ ls_b,
                             float* __restrict__ out) {
    int idx = blockIdx.x * blockDim.x + threadIdx.x;
    if (idx >= NN * 32) return;
    int n = idx >> 5;
    int c = idx & 31;
    const float* a = dAgg2 + n * L2;
    const float* w = dWgT + c * 32;
    float acc = 0.0f;
#pragma unroll
    for (int k = 0; k < 32; k++) acc += fmaxf(a[k], 0.0f) * w[k];
    dG[idx] = acc;
    float inv = 1.0f / dDeg[n];
    if (c < OUTC) out[n * OUTC + c] = acc * inv + mu_b[c];
    else          out[(size_t)NN * OUTC + n * OUTC + (c - OUTC)] = acc * inv + ls_b[c - OUTC];
}

// ---------------- kernel 6: GCN edge scatter -------------------------------
__global__ void edge3_kernel(const int* __restrict__ ei, float* __restrict__ out) {
    int idx = blockIdx.x * blockDim.x + threadIdx.x;
    if (idx >= EE * 32) return;
    int e = idx >> 5;
    int c = idx & 31;
    int s = ei[e];
    int d = ei[EE + e];
    float norm = rsqrtf(dDeg[s]) * rsqrtf(dDeg[d]);
    float v = dG[s * 32 + c] * norm;
    if (c < OUTC) atomicAdd(&out[d * OUTC + c], v);
    else          atomicAdd(&out[(size_t)NN * OUTC + d * OUTC + (c - OUTC)], v);
}

// ---------------- launch ----------------------------------------------------
extern "C" void kernel_launch(void* const* d_in, const int* in_sizes, int n_in,
                              void* d_out, int out_size) {
    const float* x     = (const float*)d_in[0];
    const int*   ei    = (const int*)  d_in[1];
    const float* ea    = (const float*)d_in[2];
    const float* nn1_w = (const float*)d_in[3];
    const float* nn1_b = (const float*)d_in[4];
    const float* root1 = (const float*)d_in[5];
    const float* bias1 = (const float*)d_in[6];
    const float* nn2_w = (const float*)d_in[7];
    const float* nn2_b = (const float*)d_in[8];
    const float* root2 = (const float*)d_in[9];
    const float* bias2 = (const float*)d_in[10];
    const float* mu_w  = (const float*)d_in[11];
    const float* mu_b  = (const float*)d_in[12];
    const float* ls_w  = (const float*)d_in[13];
    const float* ls_b  = (const float*)d_in[14];
    float* out = (float*)d_out;

    int prep_threads = C1TOT * 64 + C2TOT * 48 + 32 * 32;
    prep_weights<<<(prep_threads + 255) / 256, 256>>>(nn1_w, nn1_b, root1,
                                                      nn2_w, nn2_b, root2, mu_w, ls_w);
    node1_kernel<<<NN / NPB, 256>>>(x, bias1);
    edge1_kernel<<<(EE * L1 + 255) / 256, 256>>>(ei, ea);
    node2_kernel<<<NN / NPB, 256>>>(bias2);
    edge2_kernel<<<(EE * L2 + 255) / 256, 256>>>(ei, ea);
    node3_kernel<<<(NN * 32 + 255) / 256, 256>>>(mu_b, ls_b, out);
    edge3_kernel<<<(EE * 32 + 255) / 256, 256>>>(ei, out);
}

// round 2
// speedup vs baseline: 3.4340x; 3.4340x over previous
#include <cuda_runtime.h>
#include <cuda_bf16.h>

// Problem constants (shapes fixed by the dataset)
#define NN   8192
#define EE   65536
#define INC  64
#define OUTC 16
#define EF   8
#define L1   48
#define L2   32

// Combined column counts for the fused node transforms
#define C1TOT 480   // Y1 (EF*L1=384) + Z1 (48) + R1 (48), K=64
#define C2TOT 320   // Y2 (EF*L2=256) + Z2 (32) + R2 (32), K=48

#define NPB 8   // nodes per block (register tile height) — small enough to avoid spills

// ---------------- scratch (device globals; no allocation allowed) ----------
__device__ float dY1[(size_t)NN * EF * L1];   // [n][f*48+j]  12.6 MB
__device__ float dZ1[NN * L1];
__device__ float dAgg1[NN * L1];
__device__ float dY2[(size_t)NN * EF * L2];   // [n][f*32+j]  8.4 MB
__device__ float dZ2[NN * L2];
__device__ float dAgg2[NN * L2];
__device__ float dDeg[NN];
__device__ float dG[NN * 2 * OUTC];           // [n][c], c<16 mu, c>=16 ls
__device__ float dW1T[C1TOT * 64];            // [c][k]
__device__ float dW2T[C2TOT * 48];            // [c][k]
__device__ float dWgT[32 * 32];               // [c][k]

// ---------------- kernel 0: weight pre-transpose ---------------------------
__global__ void prep_weights(const float* __restrict__ nn1_w, const float* __restrict__ nn1_b,
                             const float* __restrict__ root1,
                             const float* __restrict__ nn2_w, const float* __restrict__ nn2_b,
                             const float* __restrict__ root2,
                             const float* __restrict__ mu_w,  const float* __restrict__ ls_w) {
    int idx = blockIdx.x * blockDim.x + threadIdx.x;
    if (idx < C1TOT * 64) {
        int c = idx >> 6, k = idx & 63;
        float v;
        if (c < EF * L1)            { int f = c / L1, j = c % L1; v = nn1_w[f * (INC * L1) + k * L1 + j]; }
        else if (c < EF * L1 + L1)  { int j = c - EF * L1;        v = nn1_b[k * L1 + j]; }
        else                        { int j = c - EF * L1 - L1;   v = root1[k * L1 + j]; }
        dW1T[idx] = v;
    }
    int i2 = idx - C1TOT * 64;
    if (i2 >= 0 && i2 < C2TOT * 48) {
        int c = i2 / 48, k = i2 % 48;
        float v;
        if (c < EF * L2)            { int f = c / L2, j = c % L2; v = nn2_w[f * (L1 * L2) + k * L2 + j]; }
        else if (c < EF * L2 + L2)  { int j = c - EF * L2;        v = nn2_b[k * L2 + j]; }
        else                        { int j = c - EF * L2 - L2;   v = root2[k * L2 + j]; }
        dW2T[i2] = v;
    }
    int i3 = i2 - C2TOT * 48;
    if (i3 >= 0 && i3 < 32 * 32) {
        int c = i3 >> 5, k = i3 & 31;
        dWgT[i3] = (c < OUTC) ? mu_w[k * OUTC + c] : ls_w[k * OUTC + (c - OUTC)];
    }
}

// ---------------- kernel 1: node transform layer 1 -------------------------
// Y1 = x@W_f (per f), Z1 = x@B1, agg1 := x@root1 + bias1 ; deg := 1
__global__ __launch_bounds__(256) void node1_kernel(const float* __restrict__ x,
                                                    const float* __restrict__ bias1) {
    __shared__ float xs[NPB * 64];
    int n0 = blockIdx.x * NPB;
    int t = threadIdx.x;
    if (t < NPB * 64 / 4)
        ((float4*)xs)[t] = ((const float4*)(x + (size_t)n0 * 64))[t];
    if (t < NPB) dDeg[n0 + t] = 1.0f;
    __syncthreads();

    for (int c = t; c < C1TOT; c += 256) {
        float acc[NPB];
#pragma unroll
        for (int n = 0; n < NPB; n++) acc[n] = 0.0f;
        const float4* w4 = (const float4*)(dW1T + c * 64);
#pragma unroll 4
        for (int k4 = 0; k4 < 16; k4++) {
            float4 w = w4[k4];
#pragma unroll
            for (int n = 0; n < NPB; n++) {
                float4 xv = ((const float4*)(xs + n * 64))[k4];
                acc[n] += xv.x * w.x + xv.y * w.y + xv.z * w.z + xv.w * w.w;
            }
        }
        if (c < EF * L1) {
#pragma unroll
            for (int n = 0; n < NPB; n++) dY1[(size_t)(n0 + n) * (EF * L1) + c] = acc[n];
        } else if (c < EF * L1 + L1) {
            int j = c - EF * L1;
#pragma unroll
            for (int n = 0; n < NPB; n++) dZ1[(n0 + n) * L1 + j] = acc[n];
        } else {
            int j = c - EF * L1 - L1;
            float b = bias1[j];
#pragma unroll
            for (int n = 0; n < NPB; n++) dAgg1[(n0 + n) * L1 + j] = acc[n] + b;
        }
    }
}

// ---------------- kernel 2: edge scatter layer 1 ---------------------------
__global__ void edge1_kernel(const int* __restrict__ ei, const float* __restrict__ ea) {
    int idx = blockIdx.x * blockDim.x + threadIdx.x;
    if (idx >= EE * L1) return;
    int e = idx / L1;
    int j = idx - e * L1;
    int s = ei[e];
    int d = ei[EE + e];
    const float* eav = ea + e * EF;
    const float* y = dY1 + (size_t)s * (EF * L1) + j;
    float m = dZ1[s * L1 + j];
#pragma unroll
    for (int f = 0; f < EF; f++) m += eav[f] * y[f * L1];
    atomicAdd(&dAgg1[d * L1 + j], m);
    if (j == 0) atomicAdd(&dDeg[d], 1.0f);
}

// ---------------- kernel 3: node transform layer 2 -------------------------
__global__ __launch_bounds__(256) void node2_kernel(const float* __restrict__ bias2) {
    __shared__ float hs[NPB * 48];
    int n0 = blockIdx.x * NPB;
    int t = threadIdx.x;
    if (t < NPB * 48 / 4) {
        float4 v = ((const float4*)(dAgg1 + n0 * L1))[t];
        v.x = fmaxf(v.x, 0.f); v.y = fmaxf(v.y, 0.f);
        v.z = fmaxf(v.z, 0.f); v.w = fmaxf(v.w, 0.f);
        ((float4*)hs)[t] = v;
    }
    __syncthreads();

    for (int c = t; c < C2TOT; c += 256) {
        float acc[NPB];
#pragma unroll
        for (int n = 0; n < NPB; n++) acc[n] = 0.0f;
        const float4* w4 = (const float4*)(dW2T + c * 48);
#pragma unroll 4
        for (int k4 = 0; k4 < 12; k4++) {
            float4 w = w4[k4];
#pragma unroll
            for (int n = 0; n < NPB; n++) {
                float4 xv = ((const float4*)(hs + n * 48))[k4];
                acc[n] += xv.x * w.x + xv.y * w.y + xv.z * w.z + xv.w * w.w;
            }
        }
        if (c < EF * L2) {
#pragma unroll
            for (int n = 0; n < NPB; n++) dY2[(size_t)(n0 + n) * (EF * L2) + c] = acc[n];
        } else if (c < EF * L2 + L2) {
            int j = c - EF * L2;
#pragma unroll
            for (int n = 0; n < NPB; n++) dZ2[(n0 + n) * L2 + j] = acc[n];
        } else {
            int j = c - EF * L2 - L2;
            float b = bias2[j];
#pragma unroll
            for (int n = 0; n < NPB; n++) dAgg2[(n0 + n) * L2 + j] = acc[n] + b;
        }
    }
}

// ---------------- kernel 4: edge scatter layer 2 ---------------------------
__global__ void edge2_kernel(const int* __restrict__ ei, const float* __restrict__ ea) {
    int idx = blockIdx.x * blockDim.x + threadIdx.x;
    if (idx >= EE * L2) return;
    int e = idx >> 5;
    int j = idx & 31;
    int s = ei[e];
    int d = ei[EE + e];
    const float* eav = ea + e * EF;
    const float* y = dY2 + (size_t)s * (EF * L2) + j;
    float m = dZ2[s * L2 + j];
#pragma unroll
    for (int f = 0; f < EF; f++) m += eav[f] * y[f * L2];
    atomicAdd(&dAgg2[d * L2 + j], m);
}

// ---------------- kernel 5: h2 relu + head GEMV + out init -----------------
__global__ void node3_kernel(const float* __restrict__ mu_b, const float* __restrict__ ls_b,
                             float* __restrict__ out) {
    int idx = blockIdx.x * blockDim.x + threadIdx.x;
    if (idx >= NN * 32) return;
    int n = idx >> 5;
    int c = idx & 31;
    const float* a = dAgg2 + n * L2;
    const float* w = dWgT + c * 32;
    float acc = 0.0f;
#pragma unroll
    for (int k = 0; k < 32; k++) acc += fmaxf(a[k], 0.0f) * w[k];
    dG[idx] = acc;
    float inv = 1.0f / dDeg[n];
    if (c < OUTC) out[n * OUTC + c] = acc * inv + mu_b[c];
    else          out[(size_t)NN * OUTC + n * OUTC + (c - OUTC)] = acc * inv + ls_b[c - OUTC];
}

// ---------------- kernel 6: GCN edge scatter -------------------------------
__global__ void edge3_kernel(const int* __restrict__ ei, float* __restrict__ out) {
    int idx = blockIdx.x * blockDim.x + threadIdx.x;
    if (idx >= EE * 32) return;
    int e = idx >> 5;
    int c = idx & 31;
    int s = ei[e];
    int d = ei[EE + e];
    float norm = rsqrtf(dDeg[s]) * rsqrtf(dDeg[d]);
    float v = dG[s * 32 + c] * norm;
    if (c < OUTC) atomicAdd(&out[d * OUTC + c], v);
    else          atomicAdd(&out[(size_t)NN * OUTC + d * OUTC + (c - OUTC)], v);
}

// ---------------- launch ----------------------------------------------------
extern "C" void kernel_launch(void* const* d_in, const int* in_sizes, int n_in,
                              void* d_out, int out_size) {
    const float* x     = (const float*)d_in[0];
    const int*   ei    = (const int*)  d_in[1];
    const float* ea    = (const float*)d_in[2];
    const float* nn1_w = (const float*)d_in[3];
    const float* nn1_b = (const float*)d_in[4];
    const float* root1 = (const float*)d_in[5];
    const float* bias1 = (const float*)d_in[6];
    const float* nn2_w = (const float*)d_in[7];
    const float* nn2_b = (const float*)d_in[8];
    const float* root2 = (const float*)d_in[9];
    const float* bias2 = (const float*)d_in[10];
    const float* mu_w  = (const float*)d_in[11];
    const float* mu_b  = (const float*)d_in[12];
    const float* ls_w  = (const float*)d_in[13];
    const float* ls_b  = (const float*)d_in[14];
    float* out = (float*)d_out;

    int prep_threads = C1TOT * 64 + C2TOT * 48 + 32 * 32;
    prep_weights<<<(prep_threads + 255) / 256, 256>>>(nn1_w, nn1_b, root1,
                                                      nn2_w, nn2_b, root2, mu_w, ls_w);
    node1_kernel<<<NN / NPB, 256>>>(x, bias1);
    edge1_kernel<<<(EE * L1 + 255) / 256, 256>>>(ei, ea);
    node2_kernel<<<NN / NPB, 256>>>(bias2);
    edge2_kernel<<<(EE * L2 + 255) / 256, 256>>>(ei, ea);
    node3_kernel<<<(NN * 32 + 255) / 256, 256>>>(mu_b, ls_b, out);
    edge3_kernel<<<(EE * 32 + 255) / 256, 256>>>(ei, out);
}

// round 3
// speedup vs baseline: 4.2632x; 1.2415x over previous
#include <cuda_runtime.h>
#include <cuda_bf16.h>

// Problem constants (shapes fixed by the dataset)
#define NN   8192
#define EE   65536
#define INC  64
#define OUTC 16
#define EF   8
#define L1   48
#define L2   32

#define C1TOT 480   // Y1 (EF*L1=384) + Z1 (48) + R1 (48), K=64
#define C2TOT 320   // Y2 (EF*L2=256) + Z2 (32) + R2 (32), K=48

#define NPB 8   // nodes per block (register tile height)

// ---------------- scratch (device globals; no allocation allowed) ----------
__device__ float dY1[(size_t)NN * EF * L1];   // [n][f*48+j]  12.6 MB
__device__ float dZ1[NN * L1];
__device__ float dAgg1[NN * L1];
__device__ float dY2[(size_t)NN * EF * L2];   // [n][f*32+j]  8.4 MB
__device__ float dZ2[NN * L2];
__device__ float dAgg2[NN * L2];
__device__ float dDeg[NN];
__device__ float dG[NN * 2 * OUTC];           // [n][c], c<16 mu, c>=16 ls
__device__ float dW1km[64 * C1TOT];           // k-major: [k][c]
__device__ float dW2km[48 * C2TOT];           // k-major: [k][c]
__device__ float dWgT[32 * 32];               // [c][k]

// ---------------- kernel 0: weight pre-transpose (k-major) ------------------
__global__ void prep_weights(const float* __restrict__ nn1_w, const float* __restrict__ nn1_b,
                             const float* __restrict__ root1,
                             const float* __restrict__ nn2_w, const float* __restrict__ nn2_b,
                             const float* __restrict__ root2,
                             const float* __restrict__ mu_w,  const float* __restrict__ ls_w) {
    int idx = blockIdx.x * blockDim.x + threadIdx.x;
    if (idx < C1TOT * 64) {
        // idx = k*C1TOT + c  (k-major output)
        int k = idx / C1TOT, c = idx - k * C1TOT;
        float v;
        if (c < EF * L1)            { int f = c / L1, j = c % L1; v = nn1_w[f * (INC * L1) + k * L1 + j]; }
        else if (c < EF * L1 + L1)  { int j = c - EF * L1;        v = nn1_b[k * L1 + j]; }
        else                        { int j = c - EF * L1 - L1;   v = root1[k * L1 + j]; }
        dW1km[idx] = v;
    }
    int i2 = idx - C1TOT * 64;
    if (i2 >= 0 && i2 < C2TOT * 48) {
        int k = i2 / C2TOT, c = i2 - k * C2TOT;
        float v;
        if (c < EF * L2)            { int f = c / L2, j = c % L2; v = nn2_w[f * (L1 * L2) + k * L2 + j]; }
        else if (c < EF * L2 + L2)  { int j = c - EF * L2;        v = nn2_b[k * L2 + j]; }
        else                        { int j = c - EF * L2 - L2;   v = root2[k * L2 + j]; }
        dW2km[i2] = v;
    }
    int i3 = i2 - C2TOT * 48;
    if (i3 >= 0 && i3 < 32 * 32) {
        int c = i3 >> 5, k = i3 & 31;
        dWgT[i3] = (c < OUTC) ? mu_w[k * OUTC + c] : ls_w[k * OUTC + (c - OUTC)];
    }
}

// ---------------- kernel 1: node transform layer 1 -------------------------
// Y1 = x@W_f (per f), Z1 = x@B1, agg1 := x@root1 + bias1 ; deg := 1
__global__ __launch_bounds__(256) void node1_kernel(const float* __restrict__ x,
                                                    const float* __restrict__ bias1) {
    __shared__ float xs[NPB * 64];
    int n0 = blockIdx.x * NPB;
    int t = threadIdx.x;
    if (t < NPB * 64 / 4)
        ((float4*)xs)[t] = ((const float4*)(x + (size_t)n0 * 64))[t];
    if (t < NPB) dDeg[n0 + t] = 1.0f;
    __syncthreads();

    for (int c = t; c < C1TOT; c += 256) {
        float acc[NPB];
#pragma unroll
        for (int n = 0; n < NPB; n++) acc[n] = 0.0f;
        const float* wp = dW1km + c;
#pragma unroll 4
        for (int k4 = 0; k4 < 16; k4++) {
            // coalesced: consecutive lanes (consecutive c) read consecutive words
            float w0 = wp[(4 * k4 + 0) * C1TOT];
            float w1 = wp[(4 * k4 + 1) * C1TOT];
            float w2 = wp[(4 * k4 + 2) * C1TOT];
            float w3 = wp[(4 * k4 + 3) * C1TOT];
#pragma unroll
            for (int n = 0; n < NPB; n++) {
                float4 xv = ((const float4*)(xs + n * 64))[k4];  // broadcast LDS
                acc[n] += xv.x * w0 + xv.y * w1 + xv.z * w2 + xv.w * w3;
            }
        }
        if (c < EF * L1) {
#pragma unroll
            for (int n = 0; n < NPB; n++) dY1[(size_t)(n0 + n) * (EF * L1) + c] = acc[n];
        } else if (c < EF * L1 + L1) {
            int j = c - EF * L1;
#pragma unroll
            for (int n = 0; n < NPB; n++) dZ1[(n0 + n) * L1 + j] = acc[n];
        } else {
            int j = c - EF * L1 - L1;
            float b = bias1[j];
#pragma unroll
            for (int n = 0; n < NPB; n++) dAgg1[(n0 + n) * L1 + j] = acc[n] + b;
        }
    }
}

// ---------------- kernel 2: edge scatter layer 1 ---------------------------
__global__ void edge1_kernel(const int* __restrict__ ei, const float* __restrict__ ea) {
    int idx = blockIdx.x * blockDim.x + threadIdx.x;
    if (idx >= EE * L1) return;
    int e = idx / L1;
    int j = idx - e * L1;
    int s = ei[e];
    int d = ei[EE + e];
    const float* eav = ea + e * EF;
    const float* y = dY1 + (size_t)s * (EF * L1) + j;
    float m = dZ1[s * L1 + j];
#pragma unroll
    for (int f = 0; f < EF; f++) m += eav[f] * y[f * L1];
    atomicAdd(&dAgg1[d * L1 + j], m);
    if (j == 0) atomicAdd(&dDeg[d], 1.0f);
}

// ---------------- kernel 3: node transform layer 2 -------------------------
__global__ __launch_bounds__(256) void node2_kernel(const float* __restrict__ bias2) {
    __shared__ float hs[NPB * 48];
    int n0 = blockIdx.x * NPB;
    int t = threadIdx.x;
    if (t < NPB * 48 / 4) {
        float4 v = ((const float4*)(dAgg1 + n0 * L1))[t];
        v.x = fmaxf(v.x, 0.f); v.y = fmaxf(v.y, 0.f);
        v.z = fmaxf(v.z, 0.f); v.w = fmaxf(v.w, 0.f);
        ((float4*)hs)[t] = v;
    }
    __syncthreads();

    for (int c = t; c < C2TOT; c += 256) {
        float acc[NPB];
#pragma unroll
        for (int n = 0; n < NPB; n++) acc[n] = 0.0f;
        const float* wp = dW2km + c;
#pragma unroll 4
        for (int k4 = 0; k4 < 12; k4++) {
            float w0 = wp[(4 * k4 + 0) * C2TOT];
            float w1 = wp[(4 * k4 + 1) * C2TOT];
            float w2 = wp[(4 * k4 + 2) * C2TOT];
            float w3 = wp[(4 * k4 + 3) * C2TOT];
#pragma unroll
            for (int n = 0; n < NPB; n++) {
                float4 xv = ((const float4*)(hs + n * 48))[k4];
                acc[n] += xv.x * w0 + xv.y * w1 + xv.z * w2 + xv.w * w3;
            }
        }
        if (c < EF * L2) {
#pragma unroll
            for (int n = 0; n < NPB; n++) dY2[(size_t)(n0 + n) * (EF * L2) + c] = acc[n];
        } else if (c < EF * L2 + L2) {
            int j = c - EF * L2;
#pragma unroll
            for (int n = 0; n < NPB; n++) dZ2[(n0 + n) * L2 + j] = acc[n];
        } else {
            int j = c - EF * L2 - L2;
            float b = bias2[j];
#pragma unroll
            for (int n = 0; n < NPB; n++) dAgg2[(n0 + n) * L2 + j] = acc[n] + b;
        }
    }
}

// ---------------- kernel 4: edge scatter layer 2 ---------------------------
__global__ void edge2_kernel(const int* __restrict__ ei, const float* __restrict__ ea) {
    int idx = blockIdx.x * blockDim.x + threadIdx.x;
    if (idx >= EE * L2) return;
    int e = idx >> 5;
    int j = idx & 31;
    int s = ei[e];
    int d = ei[EE + e];
    const float* eav = ea + e * EF;
    const float* y = dY2 + (size_t)s * (EF * L2) + j;
    float m = dZ2[s * L2 + j];
#pragma unroll
    for (int f = 0; f < EF; f++) m += eav[f] * y[f * L2];
    atomicAdd(&dAgg2[d * L2 + j], m);
}

// ---------------- kernel 5: h2 relu + head GEMV + out init -----------------
__global__ void node3_kernel(const float* __restrict__ mu_b, const float* __restrict__ ls_b,
                             float* __restrict__ out) {
    int idx = blockIdx.x * blockDim.x + threadIdx.x;
    if (idx >= NN * 32) return;
    int n = idx >> 5;
    int c = idx & 31;
    const float* a = dAgg2 + n * L2;
    const float* w = dWgT + c * 32;
    float acc = 0.0f;
#pragma unroll
    for (int k = 0; k < 32; k++) acc += fmaxf(a[k], 0.0f) * w[k];
    dG[idx] = acc;
    float inv = 1.0f / dDeg[n];
    if (c < OUTC) out[n * OUTC + c] = acc * inv + mu_b[c];
    else          out[(size_t)NN * OUTC + n * OUTC + (c - OUTC)] = acc * inv + ls_b[c - OUTC];
}

// ---------------- kernel 6: GCN edge scatter -------------------------------
__global__ void edge3_kernel(const int* __restrict__ ei, float* __restrict__ out) {
    int idx = blockIdx.x * blockDim.x + threadIdx.x;
    if (idx >= EE * 32) return;
    int e = idx >> 5;
    int c = idx & 31;
    int s = ei[e];
    int d = ei[EE + e];
    float norm = rsqrtf(dDeg[s]) * rsqrtf(dDeg[d]);
    float v = dG[s * 32 + c] * norm;
    if (c < OUTC) atomicAdd(&out[d * OUTC + c], v);
    else          atomicAdd(&out[(size_t)NN * OUTC + d * OUTC + (c - OUTC)], v);
}

// ---------------- launch ----------------------------------------------------
extern "C" void kernel_launch(void* const* d_in, const int* in_sizes, int n_in,
                              void* d_out, int out_size) {
    const float* x     = (const float*)d_in[0];
    const int*   ei    = (const int*)  d_in[1];
    const float* ea    = (const float*)d_in[2];
    const float* nn1_w = (const float*)d_in[3];
    const float* nn1_b = (const float*)d_in[4];
    const float* root1 = (const float*)d_in[5];
    const float* bias1 = (const float*)d_in[6];
    const float* nn2_w = (const float*)d_in[7];
    const float* nn2_b = (const float*)d_in[8];
    const float* root2 = (const float*)d_in[9];
    const float* bias2 = (const float*)d_in[10];
    const float* mu_w  = (const float*)d_in[11];
    const float* mu_b  = (const float*)d_in[12];
    const float* ls_w  = (const float*)d_in[13];
    const float* ls_b  = (const float*)d_in[14];
    float* out = (float*)d_out;

    int prep_threads = C1TOT * 64 + C2TOT * 48 + 32 * 32;
    prep_weights<<<(prep_threads + 255) / 256, 256>>>(nn1_w, nn1_b, root1,
                                                      nn2_w, nn2_b, root2, mu_w, ls_w);
    node1_kernel<<<NN / NPB, 256>>>(x, bias1);
    edge1_kernel<<<(EE * L1 + 255) / 256, 256>>>(ei, ea);
    node2_kernel<<<NN / NPB, 256>>>(bias2);
    edge2_kernel<<<(EE * L2 + 255) / 256, 256>>>(ei, ea);
    node3_kernel<<<(NN * 32 + 255) / 256, 256>>>(mu_b, ls_b, out);
    edge3_kernel<<<(EE * 32 + 255) / 256, 256>>>(ei, out);
}